// round 6
// baseline (speedup 1.0000x reference)
#include <cuda_runtime.h>
#include <cstdint>

// ----------------------------------------------------------------------------
// HandGNNEncoder: 2-layer GCN on a fixed 21-node skeleton + mean pool, fused.
//
// Algebra (A = normalized adjacency, constant):
//   h1 = relu( (A x) W1 + b1 )            (A x done sparse: 44 nnz, 2 feature cols)
//   out = sum_s c[s] * h1[s,:] @ W2 + b2  where c[s] = (1/21) sum_t A[t,s]
// ----------------------------------------------------------------------------

#define R2 0.70710678118654752440f   // 1/sqrt(2)
#define R3 0.57735026918962576451f   // 1/sqrt(3)
#define T3 (1.0f/3.0f)
#define W23 (R2*R3)

// CSR of incoming neighbors (incl. self-loop) per target node s.
static __device__ const int g_rowptr[22] = {
    0,1,3,5,7,9,11,13,15,17,20,22,24,26,29,31,33,35,38,40,42,44};
static __device__ const int g_cols[44] = {
    0,
    1,0,  2,1,  3,2,  4,3,
    5,0,  6,5,  7,6,  8,7,
    9,0,5,  10,9,  11,10,  12,11,
    13,0,9, 14,13, 15,14, 16,15,
    17,0,13,18,17, 19,18, 20,19};
// weight(s,u) = deg[s]^-1/2 * deg[u]^-1/2, parallel to g_cols
static __device__ const float g_w[44] = {
    1.0f,
    0.5f,R2,  0.5f,0.5f,  0.5f,0.5f,  0.5f,0.5f,
    0.5f,R2,  0.5f,0.5f,  0.5f,0.5f,  0.5f,0.5f,
    T3,R3,W23, 0.5f,W23,  0.5f,0.5f,  0.5f,0.5f,
    T3,R3,T3,  0.5f,W23,  0.5f,0.5f,  0.5f,0.5f,
    T3,R3,T3,  0.5f,W23,  0.5f,0.5f,  0.5f,0.5f};

// c[s] = (1/21) * dis[s] * sum_{t in {s} U out(s)} dis[t]   (pool-folded column sums)
__constant__ float c_c[21] = {
    (1.0f + 2.0f*R2 + 3.0f*R3)/21.0f,                      // s0
    1.0f/21.0f, 1.0f/21.0f, 1.0f/21.0f, 0.5f/21.0f,        // s1..s4
    (1.0f + W23)/21.0f, 1.0f/21.0f, 1.0f/21.0f, 0.5f/21.0f,// s5..s8
    (2.0f/3.0f + W23)/21.0f, 1.0f/21.0f, 1.0f/21.0f, 0.5f/21.0f, // s9..s12
    (2.0f/3.0f + W23)/21.0f, 1.0f/21.0f, 1.0f/21.0f, 0.5f/21.0f, // s13..s16
    (1.0f/3.0f + W23)/21.0f, 1.0f/21.0f, 1.0f/21.0f, 0.5f/21.0f  // s17..s20
};

#define NGRAPHS 32768
#define GPT     16            // graphs per tile
#define NTILES  (NGRAPHS/GPT) // 2048
#define NBLOCKS 304           // ~2 per SM, persistent

__global__ void __launch_bounds__(256, 2)
hand_gnn_kernel(const float* __restrict__ x,   // [G,21,2]
                const float* __restrict__ W1,  // [2,64]
                const float* __restrict__ b1,  // [64]
                const float* __restrict__ W2,  // [64,128]
                const float* __restrict__ b2,  // [128]
                float* __restrict__ out)       // [G,128]
{
    __shared__ float s_q[GPT * 64];   // phase1: staged x (GPT*42 <= GPT*64); phase2/3: q
    __shared__ float s_xa[GPT * 42];  // A x  (aggregated raw coords)

    const int t = threadIdx.x;

    // ---- persistent per-thread parameters ----
    // phase 3: thread owns output feature f; W2 column lives in registers
    const int f  = t & 127;
    const int gh = t >> 7;            // 0/1: which graph parity this thread covers
    float w2c[64];
#pragma unroll
    for (int d = 0; d < 64; ++d) w2c[d] = W2[d * 128 + f];
    const float b2f = b2[f];

    // phase 2: thread owns hidden channel d2
    const int d2 = t & 63;
    const float w10 = W1[d2];
    const float w11 = W1[64 + d2];
    const float b1d = b1[d2];

    for (int tile = blockIdx.x; tile < NTILES; tile += gridDim.x) {
        const int g0 = tile * GPT;

        // ---- phase 1a: stage raw x (coalesced) ----
        const float* xg = x + (size_t)g0 * 42;
        for (int i = t; i < GPT * 42; i += 256) s_q[i] = xg[i];
        __syncthreads();

        // ---- phase 1b: sparse aggregate  xa[g][s][k] = sum_u A[s,u] x[g][u][k] ----
        for (int i = t; i < GPT * 42; i += 256) {
            const int g = i / 42;
            const int j = i - g * 42;
            const int s = j >> 1;
            const int k = j & 1;
            float acc = 0.0f;
            const int e0 = g_rowptr[s], e1 = g_rowptr[s + 1];
            for (int e = e0; e < e1; ++e)
                acc = fmaf(g_w[e], s_q[g * 42 + (g_cols[e] << 1) + k], acc);
            s_xa[i] = acc;
        }
        __syncthreads();

        // ---- phase 2: q[g][d] = sum_s c[s] * relu(xa0*W1[0,d] + xa1*W1[1,d] + b1[d]) ----
        // (overwrites s_q; staged x is dead now)
#pragma unroll
        for (int it = 0; it < GPT / 4; ++it) {
            const int g = (t >> 6) + it * 4;          // warp-uniform graph id
            const float2* xa2 = (const float2*)&s_xa[g * 42];
            float acc = 0.0f;
#pragma unroll
            for (int s = 0; s < 21; ++s) {
                const float2 a = xa2[s];              // broadcast within warp
                float v = fmaf(a.x, w10, fmaf(a.y, w11, b1d));
                v = fmaxf(v, 0.0f);
                acc = fmaf(v, c_c[s], acc);
            }
            s_q[g * 64 + d2] = acc;
        }
        __syncthreads();

        // ---- phase 3: out[g][f] = q[g,:] . W2[:,f] + b2[f] ----
#pragma unroll
        for (int it = 0; it < GPT / 2; ++it) {
            const int g = gh + it * 2;                // warp-uniform graph id
            const float4* qv = (const float4*)&s_q[g * 64];
            float acc = b2f;
#pragma unroll
            for (int dq = 0; dq < 16; ++dq) {
                const float4 q4 = qv[dq];             // broadcast LDS.128
                acc = fmaf(q4.x, w2c[4 * dq + 0], acc);
                acc = fmaf(q4.y, w2c[4 * dq + 1], acc);
                acc = fmaf(q4.z, w2c[4 * dq + 2], acc);
                acc = fmaf(q4.w, w2c[4 * dq + 3], acc);
            }
            out[(size_t)(g0 + g) * 128 + f] = acc;
        }
        __syncthreads();   // protect s_q before next tile restages x
    }
}

extern "C" void kernel_launch(void* const* d_in, const int* in_sizes, int n_in,
                              void* d_out, int out_size)
{
    const float* x  = (const float*)d_in[0];  // hand_landmarks [64,512,21,2]
    const float* W1 = (const float*)d_in[1];  // [2,64]
    const float* b1 = (const float*)d_in[2];  // [64]
    const float* W2 = (const float*)d_in[3];  // [64,128]
    const float* b2 = (const float*)d_in[4];  // [128]
    float* out = (float*)d_out;               // [64,512,128]

    hand_gnn_kernel<<<NBLOCKS, 256>>>(x, W1, b1, W2, b2, out);
}